// round 11
// baseline (speedup 1.0000x reference)
#include <cuda_runtime.h>
#include <math.h>

#define BN 4
#define NX 4096
#define NYP 8192
#define GP 4096
#define CN 32
#define SN 16
#define NB 128
#define NT 512

// ---------------- scratch (static device globals; no allocation) ----------------
__device__ __align__(16) float  g_xe[BN*GP];
__device__ __align__(16) float  g_le[BN*GP*2];
__device__ __align__(16) float  g_h[2][BN*CN*GP];
__device__ __align__(16) float2 g_xf[BN*CN*16*8];
__device__ __align__(16) float2 g_of[BN*CN*16*8];
__device__ __align__(16) float2 g_Fm[BN*CN*17*9];
__device__ __align__(16) float  g_mn[BN*SN*2];
__device__ __align__(16) float  g_mx[BN*SN*2];
__device__ __align__(16) float  g_hl[BN*GP];
__device__ __align__(16) float  g_nu[BN*NYP];

// grid barrier state
__device__ unsigned g_cnt = 0;
__device__ volatile unsigned g_gen = 0;

__device__ __forceinline__ void gridbar(){
    __syncthreads();
    if (threadIdx.x == 0){
        unsigned gen = g_gen;
        __threadfence();
        unsigned old = atomicInc(&g_cnt, NB - 1);
        if (old == NB - 1){
            __threadfence();
            g_gen = gen + 1;
        } else {
            while (g_gen == gen) { __nanosleep(20); }
        }
        __threadfence();
    }
    __syncthreads();
}

__device__ __forceinline__ float wred(float v){
    #pragma unroll
    for (int o = 16; o; o >>= 1) v += __shfl_down_sync(0xffffffffu, v, o);
    return v;
}
__device__ __forceinline__ float2 cmul(float2 a, float2 b){
    return make_float2(a.x*b.x - a.y*b.y, a.x*b.y + a.y*b.x);
}
__device__ __forceinline__ float gelu(float v){
    return 0.5f*v*(1.0f + erff(v*0.70710678118654752f));
}

union SmemU {
    struct { float img[4096]; float2 t[64][9]; } fwd;
    struct { float sin_[2][32][64]; float sw[32][32]; float2 sG[2][32][8]; float2 tw[64]; } inv;
    struct { float2 sim1[17][8]; float2 sim2[9]; float2 simg[289]; } img;
    struct { float sW1[128*32]; float sb1[128]; float sW2[128]; } fc12;
    struct { float m0[NT]; float m1[NT]; float m2[NT]; float m3[NT]; } mm;
};

__global__ __launch_bounds__(NT, 1) void k_mega(
    const float* __restrict__ x,    const float* __restrict__ loc,
    const int*   __restrict__ ind,  const int*   __restrict__ sep,
    const float* __restrict__ We1,  const float* __restrict__ be1,
    const float* __restrict__ We2,  const float* __restrict__ be2,
    const float* __restrict__ Wfc0, const float* __restrict__ bfc0,
    const float* __restrict__ cw1,  const float* __restrict__ cw2,
    const float* __restrict__ wpt,  const float* __restrict__ wptb,
    const float* __restrict__ nw1,  const float* __restrict__ nw2,
    const float* __restrict__ nw,   const float* __restrict__ nb,
    const float* __restrict__ Wde3, const float* __restrict__ bde3,
    const float* __restrict__ Wfc1, const float* __restrict__ bfc1,
    const float* __restrict__ Wfc2, const float* __restrict__ bfc2,
    float* __restrict__ out)
{
    __shared__ SmemU S;
    const int bk = blockIdx.x;
    const int tid = threadIdx.x;
    const int warp = tid >> 5;
    const int lane = tid & 31;
    const int gwarp = bk*16 + warp;        // 0..2047

    // ================= PHASE E: embed1 + embed2 + minmax =================
    {
        const float4* W0 = reinterpret_cast<const float4*>(We1 + (size_t)gwarp*NX);
        const float4* W1 = reinterpret_cast<const float4*>(We1 + (size_t)(gwarp+2048)*NX);
        float a0[4] = {0,0,0,0}, a1[4] = {0,0,0,0};
        #pragma unroll 4
        for (int i = lane; i < NX/4; i += 32){
            float4 w0 = __ldg(W0 + i);
            float4 w1 = __ldg(W1 + i);
            #pragma unroll
            for (int b = 0; b < 4; b++){
                float4 xv = __ldg(reinterpret_cast<const float4*>(x + (size_t)b*NX) + i);
                a0[b] += w0.x*xv.x + w0.y*xv.y + w0.z*xv.z + w0.w*xv.w;
                a1[b] += w1.x*xv.x + w1.y*xv.y + w1.z*xv.z + w1.w*xv.w;
            }
        }
        #pragma unroll
        for (int b = 0; b < 4; b++){ a0[b] = wred(a0[b]); a1[b] = wred(a1[b]); }
        if (lane == 0){
            float b0 = __ldg(be1 + gwarp), b1 = __ldg(be1 + gwarp + 2048);
            #pragma unroll
            for (int b = 0; b < 4; b++){
                g_xe[(size_t)b*GP + gwarp]        = a0[b] + b0;
                g_xe[(size_t)b*GP + gwarp + 2048] = a1[b] + b1;
            }
        }
    }
    {
        const float4* W0 = reinterpret_cast<const float4*>(We2 + (size_t)gwarp*NYP);
        const float4* W1 = reinterpret_cast<const float4*>(We2 + (size_t)(gwarp+2048)*NYP);
        float a00[4] = {0,0,0,0}, a01[4] = {0,0,0,0};
        float a10[4] = {0,0,0,0}, a11[4] = {0,0,0,0};
        #pragma unroll 4
        for (int i = lane; i < NYP/4; i += 32){
            float4 w0 = __ldg(W0 + i);
            float4 w1 = __ldg(W1 + i);
            #pragma unroll
            for (int b = 0; b < 4; b++){
                const float4* lp = reinterpret_cast<const float4*>(loc + (size_t)b*NYP*2);
                float4 p01 = __ldg(lp + 2*i);
                float4 p23 = __ldg(lp + 2*i + 1);
                a00[b] += w0.x*p01.x + w0.y*p01.z + w0.z*p23.x + w0.w*p23.z;
                a01[b] += w0.x*p01.y + w0.y*p01.w + w0.z*p23.y + w0.w*p23.w;
                a10[b] += w1.x*p01.x + w1.y*p01.z + w1.z*p23.x + w1.w*p23.z;
                a11[b] += w1.x*p01.y + w1.y*p01.w + w1.z*p23.y + w1.w*p23.w;
            }
        }
        #pragma unroll
        for (int b = 0; b < 4; b++){
            a00[b] = wred(a00[b]); a01[b] = wred(a01[b]);
            a10[b] = wred(a10[b]); a11[b] = wred(a11[b]);
        }
        if (lane == 0){
            float b0 = __ldg(be2 + gwarp), b1 = __ldg(be2 + gwarp + 2048);
            #pragma unroll
            for (int b = 0; b < 4; b++){
                g_le[((size_t)b*GP + gwarp)*2 + 0]        = a00[b] + b0;
                g_le[((size_t)b*GP + gwarp)*2 + 1]        = a01[b] + b0;
                g_le[((size_t)b*GP + gwarp + 2048)*2 + 0] = a10[b] + b1;
                g_le[((size_t)b*GP + gwarp + 2048)*2 + 1] = a11[b] + b1;
            }
        }
    }
    if (bk < 64){
        int b = bk >> 4, s = bk & 15;
        int j0 = __ldg(sep + b*17 + s), j1 = __ldg(sep + b*17 + s + 1);
        float mn0 = 1e30f, mn1 = 1e30f, mx0 = -1e30f, mx1 = -1e30f;
        for (int j = j0 + tid; j < j1; j += NT){
            int p = __ldg(ind + (size_t)b*NYP + j);
            float l0 = __ldg(loc + ((size_t)b*NYP + p)*2);
            float l1 = __ldg(loc + ((size_t)b*NYP + p)*2 + 1);
            mn0 = fminf(mn0, l0); mx0 = fmaxf(mx0, l0);
            mn1 = fminf(mn1, l1); mx1 = fmaxf(mx1, l1);
        }
        S.mm.m0[tid] = mn0; S.mm.m1[tid] = mn1; S.mm.m2[tid] = mx0; S.mm.m3[tid] = mx1;
        __syncthreads();
        for (int st = NT/2; st; st >>= 1){
            if (tid < st){
                S.mm.m0[tid] = fminf(S.mm.m0[tid], S.mm.m0[tid+st]);
                S.mm.m1[tid] = fminf(S.mm.m1[tid], S.mm.m1[tid+st]);
                S.mm.m2[tid] = fmaxf(S.mm.m2[tid], S.mm.m2[tid+st]);
                S.mm.m3[tid] = fmaxf(S.mm.m3[tid], S.mm.m3[tid+st]);
            }
            __syncthreads();
        }
        if (tid == 0){
            g_mn[(b*SN + s)*2 + 0] = S.mm.m0[0];
            g_mn[(b*SN + s)*2 + 1] = S.mm.m1[0];
            g_mx[(b*SN + s)*2 + 0] = S.mm.m2[0];
            g_mx[(b*SN + s)*2 + 1] = S.mm.m3[0];
        }
    }
    gridbar();

    // ================= 4 spectral layers (fc0 fused into layer-0 FWD) =================
    int src = 0;
    for (int l = 0; l < 4; l++){
        // ---- FWD: block = (b,c) ----
        {
            int bc = bk;
            if (l == 0){
                int b = bc >> 5, c = bc & 31;
                float w00 = __ldg(Wfc0 + c*3), w01 = __ldg(Wfc0 + c*3 + 1), w02 = __ldg(Wfc0 + c*3 + 2);
                float bc0 = __ldg(bfc0 + c);
                const float*  xep = g_xe + (size_t)b*GP;
                const float2* lep = reinterpret_cast<const float2*>(g_le + (size_t)b*GP*2);
                float* hp0 = g_h[0] + (size_t)bc*GP;
                for (int g = tid; g < GP; g += NT){
                    float2 lv = __ldg(lep + g);
                    float v = w00*__ldg(xep + g) + w01*lv.x + w02*lv.y + bc0;
                    S.fwd.img[g] = v;
                    hp0[g] = v;
                }
            } else {
                const float4* hp = reinterpret_cast<const float4*>(g_h[src] + (size_t)bc*GP);
                float4* img4 = reinterpret_cast<float4*>(S.fwd.img);
                for (int i = tid; i < 1024; i += NT) img4[i] = hp[i];
            }
            __syncthreads();
            // phase1: thread=(x,ky); rotation twiddles
            {
                int xx = tid >> 3, ky = tid & 7;
                const float4* row = reinterpret_cast<const float4*>(S.fwd.img + (xx << 6));
                float sr, cr; sincospif(-(float)ky/32.0f, &sr, &cr);
                float2 r = make_float2(cr, sr);
                float2 w = make_float2(1.f, 0.f);
                float re = 0, im = 0;
                #pragma unroll
                for (int i = 0; i < 16; i++){
                    float4 v = row[i];
                    float2 w0 = w;
                    float2 w1 = cmul(w0, r);
                    float2 w2 = cmul(w1, r);
                    float2 w3 = cmul(w2, r);
                    w = cmul(w3, r);
                    re += v.x*w0.x + v.y*w1.x + v.z*w2.x + v.w*w3.x;
                    im += v.x*w0.y + v.y*w1.y + v.z*w2.y + v.w*w3.y;
                }
                S.fwd.t[xx][ky] = make_float2(re, im);
            }
            __syncthreads();
            // phase2: 128 outputs * 4 threads; rotation twiddles
            {
                int task = tid >> 2, sub = tid & 3;
                int kxi = task >> 3, ky = task & 7;
                int kx = (kxi < 8) ? kxi : 48 + kxi;
                float si, ci; sincospif(-(float)(kx*sub)/32.0f, &si, &ci);
                float2 w = make_float2(ci, si);
                float s4, c4; sincospif(-(float)kx/8.0f, &s4, &c4);
                float2 r4 = make_float2(c4, s4);
                float re = 0, im = 0;
                #pragma unroll
                for (int i = 0; i < 16; i++){
                    float2 tv = S.fwd.t[sub + (i << 2)][ky];
                    re += tv.x*w.x - tv.y*w.y;
                    im += tv.x*w.y + tv.y*w.x;
                    w = cmul(w, r4);
                }
                re += __shfl_down_sync(0xffffffffu, re, 2);
                im += __shfl_down_sync(0xffffffffu, im, 2);
                re += __shfl_down_sync(0xffffffffu, re, 1);
                im += __shfl_down_sync(0xffffffffu, im, 1);
                if (sub == 0) g_xf[(size_t)bc*128 + task] = make_float2(re, im);
            }
        }
        gridbar();

        // ---- MIX: 16384 outputs x 4-thread i-split over ALL 128 blocks ----
        {
            int t = bk*NT + tid;             // 0..65535
            int outi = t >> 2, sub = t & 3;  // outi 0..16383
            int b = outi >> 12, rem = outi & 4095;
            int o = rem >> 7, m = rem & 127;
            int kxi = m >> 3, mm = m & 7;
            const float* wb = (kxi < 8) ? cw1 : cw2;
            int mx = (kxi < 8) ? kxi : kxi - 8;
            const float2* wb2 = reinterpret_cast<const float2*>(
                wb + (size_t)l*65536 + (size_t)o*128 + mx*16 + mm*2);
            const float2* xfp = g_xf + (size_t)b*CN*128 + m;
            float re = 0, im = 0;
            #pragma unroll
            for (int k = 0; k < 8; k++){
                int i = sub + (k << 2);
                float2 w = __ldg(wb2 + (size_t)i*2048);
                float2 xv = __ldg(xfp + (size_t)i*128);
                re += xv.x*w.x - xv.y*w.y;
                im += xv.x*w.y + xv.y*w.x;
            }
            re += __shfl_down_sync(0xffffffffu, re, 2);
            im += __shfl_down_sync(0xffffffffu, im, 2);
            re += __shfl_down_sync(0xffffffffu, re, 1);
            im += __shfl_down_sync(0xffffffffu, im, 1);
            if (sub == 0) g_of[(size_t)(b*CN + o)*128 + m] = make_float2(re, im);
        }
        gridbar();

        // ---- INV: 256 tasks (b,x), 2 per block; twiddle TABLE (no per-thread MUFU) ----
        {
            int sub = tid >> 8, stid = tid & 255;
            int task = bk*2 + sub;
            int b = task >> 6, xx = task & 63;
            const float* hb = g_h[src] + (size_t)b*CN*GP + (xx << 6);
            for (int i = stid; i < 512; i += 256){
                int c = i >> 4, q = i & 15;
                reinterpret_cast<float4*>(S.inv.sin_[sub][c])[q] =
                    __ldg(reinterpret_cast<const float4*>(hb + (size_t)c*GP) + q);
            }
            for (int i = tid; i < 1024; i += NT) S.inv.sw[i >> 5][i & 31] = __ldg(wpt + l*1024 + i);
            if (tid < 64){ float s, c; sincospif((float)tid/32.0f, &s, &c); S.inv.tw[tid] = make_float2(c, s); }
            __syncthreads();
            // spectral x-phase: table lookups (w_j = tw[(j*xx)&63])
            {
                int o = stid >> 3, ky = stid & 7;
                const float2* ofp = g_of + (size_t)(b*CN + o)*128 + ky;
                float2 v0 = __ldg(ofp);
                float re = v0.x, im = v0.y;
                int idx = 0;
                #pragma unroll
                for (int j = 1; j <= 8; j++){
                    idx = (idx + xx) & 63;
                    float2 w = S.inv.tw[idx];
                    if (j < 8){
                        float2 a = __ldg(ofp + j*8);
                        re += a.x*w.x - a.y*w.y;
                        im += a.x*w.y + a.y*w.x;
                    }
                    float2 bm = __ldg(ofp + (16-j)*8);
                    re += bm.x*w.x + bm.y*w.y;
                    im += bm.y*w.x - bm.x*w.y;
                }
                S.inv.sG[sub][o][ky] = make_float2(re, im);
            }
            __syncthreads();
            float* outp = g_h[src^1] + (size_t)b*CN*GP + (xx << 6);
            int dogelu = (l < 3);
            #pragma unroll
            for (int k = 0; k < 2; k++){
                int task2 = k*256 + stid;
                int o = task2 >> 4, y4 = task2 & 15;
                float4 acc = make_float4(0.f, 0.f, 0.f, 0.f);
                #pragma unroll 8
                for (int c = 0; c < 32; c++){
                    float wv = S.inv.sw[o][c];
                    float4 v = reinterpret_cast<const float4*>(S.inv.sin_[sub][c])[y4];
                    acc.x += wv*v.x; acc.y += wv*v.y; acc.z += wv*v.z; acc.w += wv*v.w;
                }
                float2 G[8];
                #pragma unroll
                for (int ky = 0; ky < 8; ky++) G[ky] = S.inv.sG[sub][o][ky];
                float spec[4];
                #pragma unroll
                for (int j = 0; j < 4; j++){
                    int y = y4*4 + j;
                    float sp = G[0].x;
                    int idx = 0;
                    #pragma unroll
                    for (int ky = 1; ky < 8; ky++){
                        idx = (idx + y) & 63;
                        float2 w = S.inv.tw[idx];
                        sp += 2.0f*(G[ky].x*w.x - G[ky].y*w.y);
                    }
                    spec[j] = sp;
                }
                float bb = __ldg(wptb + l*32 + o);
                float4 r;
                r.x = acc.x + bb + spec[0]*(1.0f/4096.0f);
                r.y = acc.y + bb + spec[1]*(1.0f/4096.0f);
                r.z = acc.z + bb + spec[2]*(1.0f/4096.0f);
                r.w = acc.w + bb + spec[3]*(1.0f/4096.0f);
                if (dogelu){ r.x = gelu(r.x); r.y = gelu(r.y); r.z = gelu(r.z); r.w = gelu(r.w); }
                reinterpret_cast<float4*>(outp + (size_t)o*GP)[y4] = r;
            }
        }
        gridbar();
        src ^= 1;
    }
    // src == 0: final h in g_h[0]

    // ================= NUFWD: block = (b,c), rotation twiddles ================
    {
        int bc = bk;
        const float4* hp = reinterpret_cast<const float4*>(g_h[src] + (size_t)bc*GP);
        float4* img4 = reinterpret_cast<float4*>(S.fwd.img);
        for (int i = tid; i < 1024; i += NT) img4[i] = hp[i];
        __syncthreads();
        for (int task = tid; task < 576; task += NT){
            int xx = task/9, bb2 = task - xx*9;
            int pb = bb2 + 57; if (pb >= 65) pb -= 65;
            const float4* row = reinterpret_cast<const float4*>(S.fwd.img + (xx << 6));
            float sr, cr; sincospif(-2.0f*(float)pb/65.0f, &sr, &cr);
            float2 r = make_float2(cr, sr);
            float2 w = make_float2(1.f, 0.f);
            float re = 0, im = 0;
            #pragma unroll
            for (int i = 0; i < 16; i++){
                float4 v = row[i];
                float2 w0 = w;
                float2 w1 = cmul(w0, r);
                float2 w2 = cmul(w1, r);
                float2 w3 = cmul(w2, r);
                w = cmul(w3, r);
                re += v.x*w0.x + v.y*w1.x + v.z*w2.x + v.w*w3.x;
                im += v.x*w0.y + v.y*w1.y + v.z*w2.y + v.w*w3.y;
            }
            S.fwd.t[xx][bb2] = make_float2(re, im);
        }
        __syncthreads();
        if (tid < 320){
            int task = tid >> 1, sub = tid & 1;
            int ai = task/9, bb2 = task - ai*9;
            int pa = ai + 57; if (pa >= 65) pa -= 65;
            float si, ci; sincospif(-2.0f*(float)(pa*sub)/65.0f, &si, &ci);
            float2 w = make_float2(ci, si);
            float ss, cs; sincospif(-4.0f*(float)pa/65.0f, &ss, &cs);
            float2 rs = make_float2(cs, ss);
            float re = 0, im = 0;
            #pragma unroll
            for (int i = 0; i < 32; i++){
                float2 tv = S.fwd.t[sub + (i << 1)][bb2 < 9 ? bb2 : 0];
                re += tv.x*w.x - tv.y*w.y;
                im += tv.x*w.y + tv.y*w.x;
                w = cmul(w, rs);
            }
            re += __shfl_down_sync(0xffffffffu, re, 1);
            im += __shfl_down_sync(0xffffffffu, im, 1);
            if (sub == 0 && task < 153)
                g_Fm[(size_t)bc*153 + task] = make_float2(re*(1.0f/65.0f), im*(1.0f/65.0f));
        }
    }
    gridbar();

    // ================= IMAGES+NUDFT (blocks 0..63) + FC12 (blocks 64..127, 2-thread split) ================
    if (bk < 64){
        int b = bk >> 4, s = bk & 15;
        const float2* Fb = g_Fm + (size_t)b*CN*153;
        if (tid < 145){
            if (tid < 136){
                int ai = tid >> 3, bi = tid & 7;
                const float2* w = reinterpret_cast<const float2*>(nw1 + (size_t)s*272 + ai*16 + bi*2);
                float re = 0, im = 0;
                #pragma unroll 8
                for (int c = 0; c < 32; c++){
                    float2 f = __ldg(Fb + c*153 + ai*9 + bi);
                    float2 wv = __ldg(w + (size_t)c*2176);
                    re += f.x*wv.x - f.y*wv.y;
                    im += f.x*wv.y + f.y*wv.x;
                }
                S.img.sim1[ai][bi] = make_float2(re, im);
            } else {
                int ai = tid - 136;
                const float2* w = reinterpret_cast<const float2*>(nw2 + (size_t)s*18 + ai*2);
                float re = 0, im = 0;
                #pragma unroll 8
                for (int c = 0; c < 32; c++){
                    float2 f = __ldg(Fb + c*153 + ai*9 + 8);
                    float2 wv = __ldg(w + (size_t)c*144);
                    re += f.x*wv.x - f.y*wv.y;
                    im += f.x*wv.y + f.y*wv.x;
                }
                S.img.sim2[ai] = make_float2(re, im);
            }
        }
        __syncthreads();
        if (tid < 289){
            int xx = tid/17, yy = tid%17;
            float2 v;
            if (yy < 8)       v = S.img.sim1[xx][yy];
            else if (yy > 8){ float2 u = S.img.sim1[16-xx][16-yy]; v = make_float2(u.x, -u.y); }
            else {
                if (xx < 8)        v = S.img.sim2[xx];
                else if (xx == 8)  v = make_float2(S.img.sim2[8].x, 0.0f);
                else             { float2 u = S.img.sim2[16-xx]; v = make_float2(u.x, -u.y); }
            }
            S.img.simg[tid] = v;
        }
        __syncthreads();
        int j0 = __ldg(sep + b*17 + s), j1 = __ldg(sep + b*17 + s + 1);
        float mn0 = g_mn[(b*SN+s)*2], mn1 = g_mn[(b*SN+s)*2+1];
        float mx0 = g_mx[(b*SN+s)*2], mx1 = g_mx[(b*SN+s)*2+1];
        float wS = __ldg(nw + s), bS = __ldg(nb + s);
        for (int j = j0 + tid; j < j1; j += NT){
            int p = __ldg(ind + (size_t)b*NYP + j);
            float l0 = __ldg(loc + ((size_t)b*NYP + p)*2);
            float l1 = __ldg(loc + ((size_t)b*NYP + p)*2 + 1);
            float om0 = (l0 - mn0)/(mx0 - mn0 + 1e-6f)*6.283185307179586f - 3.141592653589793f;
            float om1 = (l1 - mn1)/(mx1 - mn1 + 1e-6f)*6.283185307179586f - 3.141592653589793f;
            float sx, cx; sincosf(om0, &sx, &cx); float2 e0 = make_float2(cx, sx);
            float sy, cy; sincosf(om1, &sy, &cy); float2 e1 = make_float2(cy, sy);
            float2 ey[17];
            ey[8] = make_float2(1.f, 0.f);
            #pragma unroll
            for (int k = 9; k < 17; k++) ey[k] = cmul(ey[k-1], e1);
            #pragma unroll
            for (int k = 0; k < 8; k++) ey[k] = make_float2(ey[16-k].x, -ey[16-k].y);
            float2 e2v = cmul(e0, e0), e4v = cmul(e2v, e2v), e8v = cmul(e4v, e4v);
            float2 exc = make_float2(e8v.x, -e8v.y);
            float acc = 0;
            #pragma unroll
            for (int xx = 0; xx < 17; xx++){
                float rr = 0, ri = 0;
                #pragma unroll
                for (int yy = 0; yy < 17; yy++){
                    float2 a = S.img.simg[xx*17 + yy];
                    float2 e = ey[yy];
                    rr += a.x*e.x - a.y*e.y;
                    ri += a.x*e.y + a.y*e.x;
                }
                acc += rr*exc.x - ri*exc.y;
                exc = cmul(exc, e0);
            }
            g_nu[(size_t)b*NYP + p] = acc*(1.0f/17.0f)*wS + bS;
        }
    } else {
        // FC12 on 64 blocks, 2 threads per point (j-loop split 64/64, shfl combine)
        for (int i = tid; i < 4096; i += NT) S.fc12.sW1[i] = __ldg(Wfc1 + i);
        if (tid < 128){ S.fc12.sb1[tid] = __ldg(bfc1 + tid); S.fc12.sW2[tid] = __ldg(Wfc2 + tid); }
        __syncthreads();
        int pt = ((bk - 64)*NT + tid) >> 1;     // 0..16383
        int half = tid & 1;
        int b = pt >> 12, g = pt & (GP-1);
        float hv[32];
        #pragma unroll
        for (int c = 0; c < 32; c++) hv[c] = g_h[src][(size_t)(b*CN + c)*GP + g];
        float acc = 0;
        int jbase = half*64;
        #pragma unroll 4
        for (int jj = 0; jj < 64; jj++){
            int j = jbase + jj;
            float a = S.fc12.sb1[j];
            #pragma unroll
            for (int c = 0; c < 32; c++) a += S.fc12.sW1[j*32 + c]*hv[c];
            a = gelu(a);
            acc += a*S.fc12.sW2[j];
        }
        acc += __shfl_down_sync(0xffffffffu, acc, 1);
        if (half == 0) g_hl[pt] = acc + __ldg(bfc2);
    }
    gridbar();

    // ================= DE3: 4 rows per warp, interleaved ================
    {
        const float4* W0 = reinterpret_cast<const float4*>(Wde3 + (size_t)gwarp*GP);
        const float4* W1 = reinterpret_cast<const float4*>(Wde3 + (size_t)(gwarp+2048)*GP);
        const float4* W2 = reinterpret_cast<const float4*>(Wde3 + (size_t)(gwarp+4096)*GP);
        const float4* W3 = reinterpret_cast<const float4*>(Wde3 + (size_t)(gwarp+6144)*GP);
        float acc[4][4];
        #pragma unroll
        for (int r = 0; r < 4; r++)
            #pragma unroll
            for (int b = 0; b < 4; b++) acc[r][b] = 0.f;
        #pragma unroll 2
        for (int i = lane; i < GP/4; i += 32){
            float4 w0 = __ldg(W0 + i);
            float4 w1 = __ldg(W1 + i);
            float4 w2 = __ldg(W2 + i);
            float4 w3 = __ldg(W3 + i);
            #pragma unroll
            for (int b = 0; b < 4; b++){
                float4 h = *reinterpret_cast<const float4*>(g_hl + (size_t)b*GP + 4*i);
                acc[0][b] += w0.x*h.x + w0.y*h.y + w0.z*h.z + w0.w*h.w;
                acc[1][b] += w1.x*h.x + w1.y*h.y + w1.z*h.z + w1.w*h.w;
                acc[2][b] += w2.x*h.x + w2.y*h.y + w2.z*h.z + w2.w*h.w;
                acc[3][b] += w3.x*h.x + w3.y*h.y + w3.z*h.z + w3.w*h.w;
            }
        }
        #pragma unroll
        for (int r = 0; r < 4; r++){
            #pragma unroll
            for (int b = 0; b < 4; b++) acc[r][b] = wred(acc[r][b]);
        }
        if (lane == 0){
            #pragma unroll
            for (int r = 0; r < 4; r++){
                int row = gwarp + r*2048;
                float bv = __ldg(bde3 + row);
                #pragma unroll
                for (int b = 0; b < 4; b++)
                    out[(size_t)b*NYP + row] = acc[r][b] + bv + g_nu[(size_t)b*NYP + row];
            }
        }
    }
}

// ---------------- host launcher ----------------
extern "C" void kernel_launch(void* const* d_in, const int* in_sizes, int n_in,
                              void* d_out, int out_size){
    k_mega<<<NB, NT>>>(
        (const float*)d_in[0],  (const float*)d_in[1],
        (const int*)  d_in[2],  (const int*)  d_in[3],
        (const float*)d_in[4],  (const float*)d_in[5],
        (const float*)d_in[6],  (const float*)d_in[7],
        (const float*)d_in[8],  (const float*)d_in[9],
        (const float*)d_in[10], (const float*)d_in[11],
        (const float*)d_in[12], (const float*)d_in[13],
        (const float*)d_in[14], (const float*)d_in[15],
        (const float*)d_in[16], (const float*)d_in[17],
        (const float*)d_in[18], (const float*)d_in[19],
        (const float*)d_in[20], (const float*)d_in[21],
        (const float*)d_in[22], (const float*)d_in[23],
        (float*)d_out);
}

// round 12
// speedup vs baseline: 1.0546x; 1.0546x over previous
#include <cuda_runtime.h>
#include <math.h>

#define BN 4
#define NX 4096
#define NYP 8192
#define GP 4096
#define CN 32
#define SN 16
#define NB 128
#define NT 512

// ---------------- scratch (static device globals; no allocation) ----------------
__device__ __align__(16) float  g_xe[BN*GP];
__device__ __align__(16) float  g_le[BN*GP*2];
__device__ __align__(16) float  g_h[2][BN*CN*GP];
__device__ __align__(16) float2 g_xf[BN*CN*16*8];
__device__ __align__(16) float2 g_of[BN*CN*16*8];
__device__ __align__(16) float2 g_Fm[BN*CN*17*9];
__device__ __align__(16) float  g_mn[BN*SN*2];
__device__ __align__(16) float  g_mx[BN*SN*2];
__device__ __align__(16) float  g_hl[BN*GP];
__device__ __align__(16) float  g_nu[BN*NYP];

// grid barrier state
__device__ unsigned g_cnt = 0;
__device__ volatile unsigned g_gen = 0;

__device__ __forceinline__ void gridbar(){
    __syncthreads();
    if (threadIdx.x == 0){
        unsigned gen = g_gen;
        __threadfence();
        unsigned old = atomicInc(&g_cnt, NB - 1);
        if (old == NB - 1){
            __threadfence();
            g_gen = gen + 1;
        } else {
            while (g_gen == gen) { __nanosleep(20); }
        }
        __threadfence();
    }
    __syncthreads();
}

__device__ __forceinline__ float wred(float v){
    #pragma unroll
    for (int o = 16; o; o >>= 1) v += __shfl_down_sync(0xffffffffu, v, o);
    return v;
}
__device__ __forceinline__ float2 cmul(float2 a, float2 b){
    return make_float2(a.x*b.x - a.y*b.y, a.x*b.y + a.y*b.x);
}
__device__ __forceinline__ float gelu(float v){
    return 0.5f*v*(1.0f + erff(v*0.70710678118654752f));
}

union SmemU {
    struct { float img[4096]; float2 t[64][9]; } fwd;
    struct { float sin_[2][32][64]; float sw[32][32]; float2 sG[2][32][8]; } inv;
    struct { float2 sim1[17][8]; float2 sim2[9]; float2 simg[289]; } img;
    struct { float sW1[128*32]; float sb1[128]; float sW2[128]; } fc12;
    struct { float m0[NT]; float m1[NT]; float m2[NT]; float m3[NT]; } mm;
};

__global__ __launch_bounds__(NT, 1) void k_mega(
    const float* __restrict__ x,    const float* __restrict__ loc,
    const int*   __restrict__ ind,  const int*   __restrict__ sep,
    const float* __restrict__ We1,  const float* __restrict__ be1,
    const float* __restrict__ We2,  const float* __restrict__ be2,
    const float* __restrict__ Wfc0, const float* __restrict__ bfc0,
    const float* __restrict__ cw1,  const float* __restrict__ cw2,
    const float* __restrict__ wpt,  const float* __restrict__ wptb,
    const float* __restrict__ nw1,  const float* __restrict__ nw2,
    const float* __restrict__ nw,   const float* __restrict__ nb,
    const float* __restrict__ Wde3, const float* __restrict__ bde3,
    const float* __restrict__ Wfc1, const float* __restrict__ bfc1,
    const float* __restrict__ Wfc2, const float* __restrict__ bfc2,
    float* __restrict__ out)
{
    __shared__ SmemU S;
    const int bk = blockIdx.x;
    const int tid = threadIdx.x;
    const int warp = tid >> 5;
    const int lane = tid & 31;
    const int gwarp = bk*16 + warp;        // 0..2047

    // ================= PHASE E: embed1 + embed2 + minmax =================
    {
        const float4* W0 = reinterpret_cast<const float4*>(We1 + (size_t)gwarp*NX);
        const float4* W1 = reinterpret_cast<const float4*>(We1 + (size_t)(gwarp+2048)*NX);
        float a0[4] = {0,0,0,0}, a1[4] = {0,0,0,0};
        #pragma unroll 4
        for (int i = lane; i < NX/4; i += 32){
            float4 w0 = __ldg(W0 + i);
            float4 w1 = __ldg(W1 + i);
            #pragma unroll
            for (int b = 0; b < 4; b++){
                float4 xv = __ldg(reinterpret_cast<const float4*>(x + (size_t)b*NX) + i);
                a0[b] += w0.x*xv.x + w0.y*xv.y + w0.z*xv.z + w0.w*xv.w;
                a1[b] += w1.x*xv.x + w1.y*xv.y + w1.z*xv.z + w1.w*xv.w;
            }
        }
        #pragma unroll
        for (int b = 0; b < 4; b++){ a0[b] = wred(a0[b]); a1[b] = wred(a1[b]); }
        if (lane == 0){
            float b0 = __ldg(be1 + gwarp), b1 = __ldg(be1 + gwarp + 2048);
            #pragma unroll
            for (int b = 0; b < 4; b++){
                g_xe[(size_t)b*GP + gwarp]        = a0[b] + b0;
                g_xe[(size_t)b*GP + gwarp + 2048] = a1[b] + b1;
            }
        }
    }
    {
        const float4* W0 = reinterpret_cast<const float4*>(We2 + (size_t)gwarp*NYP);
        const float4* W1 = reinterpret_cast<const float4*>(We2 + (size_t)(gwarp+2048)*NYP);
        float a00[4] = {0,0,0,0}, a01[4] = {0,0,0,0};
        float a10[4] = {0,0,0,0}, a11[4] = {0,0,0,0};
        #pragma unroll 4
        for (int i = lane; i < NYP/4; i += 32){
            float4 w0 = __ldg(W0 + i);
            float4 w1 = __ldg(W1 + i);
            #pragma unroll
            for (int b = 0; b < 4; b++){
                const float4* lp = reinterpret_cast<const float4*>(loc + (size_t)b*NYP*2);
                float4 p01 = __ldg(lp + 2*i);
                float4 p23 = __ldg(lp + 2*i + 1);
                a00[b] += w0.x*p01.x + w0.y*p01.z + w0.z*p23.x + w0.w*p23.z;
                a01[b] += w0.x*p01.y + w0.y*p01.w + w0.z*p23.y + w0.w*p23.w;
                a10[b] += w1.x*p01.x + w1.y*p01.z + w1.z*p23.x + w1.w*p23.z;
                a11[b] += w1.x*p01.y + w1.y*p01.w + w1.z*p23.y + w1.w*p23.w;
            }
        }
        #pragma unroll
        for (int b = 0; b < 4; b++){
            a00[b] = wred(a00[b]); a01[b] = wred(a01[b]);
            a10[b] = wred(a10[b]); a11[b] = wred(a11[b]);
        }
        if (lane == 0){
            float b0 = __ldg(be2 + gwarp), b1 = __ldg(be2 + gwarp + 2048);
            #pragma unroll
            for (int b = 0; b < 4; b++){
                g_le[((size_t)b*GP + gwarp)*2 + 0]        = a00[b] + b0;
                g_le[((size_t)b*GP + gwarp)*2 + 1]        = a01[b] + b0;
                g_le[((size_t)b*GP + gwarp + 2048)*2 + 0] = a10[b] + b1;
                g_le[((size_t)b*GP + gwarp + 2048)*2 + 1] = a11[b] + b1;
            }
        }
    }
    if (bk < 64){
        int b = bk >> 4, s = bk & 15;
        int j0 = __ldg(sep + b*17 + s), j1 = __ldg(sep + b*17 + s + 1);
        float mn0 = 1e30f, mn1 = 1e30f, mx0 = -1e30f, mx1 = -1e30f;
        for (int j = j0 + tid; j < j1; j += NT){
            int p = __ldg(ind + (size_t)b*NYP + j);
            float l0 = __ldg(loc + ((size_t)b*NYP + p)*2);
            float l1 = __ldg(loc + ((size_t)b*NYP + p)*2 + 1);
            mn0 = fminf(mn0, l0); mx0 = fmaxf(mx0, l0);
            mn1 = fminf(mn1, l1); mx1 = fmaxf(mx1, l1);
        }
        S.mm.m0[tid] = mn0; S.mm.m1[tid] = mn1; S.mm.m2[tid] = mx0; S.mm.m3[tid] = mx1;
        __syncthreads();
        for (int st = NT/2; st; st >>= 1){
            if (tid < st){
                S.mm.m0[tid] = fminf(S.mm.m0[tid], S.mm.m0[tid+st]);
                S.mm.m1[tid] = fminf(S.mm.m1[tid], S.mm.m1[tid+st]);
                S.mm.m2[tid] = fmaxf(S.mm.m2[tid], S.mm.m2[tid+st]);
                S.mm.m3[tid] = fmaxf(S.mm.m3[tid], S.mm.m3[tid+st]);
            }
            __syncthreads();
        }
        if (tid == 0){
            g_mn[(b*SN + s)*2 + 0] = S.mm.m0[0];
            g_mn[(b*SN + s)*2 + 1] = S.mm.m1[0];
            g_mx[(b*SN + s)*2 + 0] = S.mm.m2[0];
            g_mx[(b*SN + s)*2 + 1] = S.mm.m3[0];
        }
    }
    gridbar();

    // ================= 4 spectral layers (fc0 fused into layer-0 FWD) =================
    int src = 0;
    for (int l = 0; l < 4; l++){
        // ---- FWD: block = (b,c) ----
        {
            int bc = bk;
            if (l == 0){
                int b = bc >> 5, c = bc & 31;
                float w00 = __ldg(Wfc0 + c*3), w01 = __ldg(Wfc0 + c*3 + 1), w02 = __ldg(Wfc0 + c*3 + 2);
                float bc0 = __ldg(bfc0 + c);
                const float*  xep = g_xe + (size_t)b*GP;
                const float2* lep = reinterpret_cast<const float2*>(g_le + (size_t)b*GP*2);
                float* hp0 = g_h[0] + (size_t)bc*GP;
                for (int g = tid; g < GP; g += NT){
                    float2 lv = __ldg(lep + g);
                    float v = w00*__ldg(xep + g) + w01*lv.x + w02*lv.y + bc0;
                    S.fwd.img[g] = v;
                    hp0[g] = v;
                }
            } else {
                const float4* hp = reinterpret_cast<const float4*>(g_h[src] + (size_t)bc*GP);
                float4* img4 = reinterpret_cast<float4*>(S.fwd.img);
                for (int i = tid; i < 1024; i += NT) img4[i] = hp[i];
            }
            __syncthreads();
            // phase1: thread=(x,ky); rotation twiddles
            {
                int xx = tid >> 3, ky = tid & 7;
                const float4* row = reinterpret_cast<const float4*>(S.fwd.img + (xx << 6));
                float sr, cr; sincospif(-(float)ky/32.0f, &sr, &cr);
                float2 r = make_float2(cr, sr);
                float2 w = make_float2(1.f, 0.f);
                float re = 0, im = 0;
                #pragma unroll
                for (int i = 0; i < 16; i++){
                    float4 v = row[i];
                    float2 w0 = w;
                    float2 w1 = cmul(w0, r);
                    float2 w2 = cmul(w1, r);
                    float2 w3 = cmul(w2, r);
                    w = cmul(w3, r);
                    re += v.x*w0.x + v.y*w1.x + v.z*w2.x + v.w*w3.x;
                    im += v.x*w0.y + v.y*w1.y + v.z*w2.y + v.w*w3.y;
                }
                S.fwd.t[xx][ky] = make_float2(re, im);
            }
            __syncthreads();
            // phase2: 128 outputs * 4 threads; rotation twiddles
            {
                int task = tid >> 2, sub = tid & 3;
                int kxi = task >> 3, ky = task & 7;
                int kx = (kxi < 8) ? kxi : 48 + kxi;
                float si, ci; sincospif(-(float)(kx*sub)/32.0f, &si, &ci);
                float2 w = make_float2(ci, si);
                float s4, c4; sincospif(-(float)kx/8.0f, &s4, &c4);
                float2 r4 = make_float2(c4, s4);
                float re = 0, im = 0;
                #pragma unroll
                for (int i = 0; i < 16; i++){
                    float2 tv = S.fwd.t[sub + (i << 2)][ky];
                    re += tv.x*w.x - tv.y*w.y;
                    im += tv.x*w.y + tv.y*w.x;
                    w = cmul(w, r4);
                }
                re += __shfl_down_sync(0xffffffffu, re, 2);
                im += __shfl_down_sync(0xffffffffu, im, 2);
                re += __shfl_down_sync(0xffffffffu, re, 1);
                im += __shfl_down_sync(0xffffffffu, im, 1);
                if (sub == 0) g_xf[(size_t)bc*128 + task] = make_float2(re, im);
            }
        }
        gridbar();

        // ---- MIX: 16384 outputs x 4-thread i-split over ALL 128 blocks ----
        {
            int t = bk*NT + tid;             // 0..65535
            int outi = t >> 2, sub = t & 3;  // outi 0..16383
            int b = outi >> 12, rem = outi & 4095;
            int o = rem >> 7, m = rem & 127;
            int kxi = m >> 3, mm = m & 7;
            const float* wb = (kxi < 8) ? cw1 : cw2;
            int mx = (kxi < 8) ? kxi : kxi - 8;
            const float2* wb2 = reinterpret_cast<const float2*>(
                wb + (size_t)l*65536 + (size_t)o*128 + mx*16 + mm*2);
            const float2* xfp = g_xf + (size_t)b*CN*128 + m;
            float re = 0, im = 0;
            #pragma unroll
            for (int k = 0; k < 8; k++){
                int i = sub + (k << 2);
                float2 w = __ldg(wb2 + (size_t)i*2048);
                float2 xv = __ldg(xfp + (size_t)i*128);
                re += xv.x*w.x - xv.y*w.y;
                im += xv.x*w.y + xv.y*w.x;
            }
            re += __shfl_down_sync(0xffffffffu, re, 2);
            im += __shfl_down_sync(0xffffffffu, im, 2);
            re += __shfl_down_sync(0xffffffffu, re, 1);
            im += __shfl_down_sync(0xffffffffu, im, 1);
            if (sub == 0) g_of[(size_t)(b*CN + o)*128 + m] = make_float2(re, im);
        }
        gridbar();

        // ---- INV: 256 tasks (b,x), 2 per block; synthesis: 2 outputs/thread share LDS ----
        {
            int sub = tid >> 8, stid = tid & 255;
            int task = bk*2 + sub;
            int b = task >> 6, xx = task & 63;
            const float* hb = g_h[src] + (size_t)b*CN*GP + (xx << 6);
            for (int i = stid; i < 512; i += 256){
                int c = i >> 4, q = i & 15;
                reinterpret_cast<float4*>(S.inv.sin_[sub][c])[q] =
                    __ldg(reinterpret_cast<const float4*>(hb + (size_t)c*GP) + q);
            }
            for (int i = tid; i < 1024; i += NT) S.inv.sw[i >> 5][i & 31] = __ldg(wpt + l*1024 + i);
            __syncthreads();
            // spectral x-phase: rotation twiddles (R10 version)
            {
                int o = stid >> 3, ky = stid & 7;
                const float2* ofp = g_of + (size_t)(b*CN + o)*128 + ky;
                float sr, cr; sincospif((float)xx/32.0f, &sr, &cr);
                float2 r = make_float2(cr, sr);
                float2 w = make_float2(1.f, 0.f);
                float2 v0 = __ldg(ofp);
                float re = v0.x, im = v0.y;
                #pragma unroll
                for (int j = 1; j <= 8; j++){
                    w = cmul(w, r);
                    if (j < 8){
                        float2 a = __ldg(ofp + j*8);
                        re += a.x*w.x - a.y*w.y;
                        im += a.x*w.y + a.y*w.x;
                    }
                    float2 bm = __ldg(ofp + (16-j)*8);
                    re += bm.x*w.x + bm.y*w.y;
                    im += bm.y*w.x - bm.x*w.y;
                }
                S.inv.sG[sub][o][ky] = make_float2(re, im);
            }
            __syncthreads();
            float* outp = g_h[src^1] + (size_t)b*CN*GP + (xx << 6);
            int dogelu = (l < 3);
            // synthesis: thread = (o0 in [0,16), y4); outputs o0 and o0+16
            {
                int o0 = stid >> 4, y4 = stid & 15;
                int o1 = o0 + 16;
                float4 acc0 = make_float4(0.f,0.f,0.f,0.f);
                float4 acc1 = make_float4(0.f,0.f,0.f,0.f);
                #pragma unroll 8
                for (int c = 0; c < 32; c++){
                    float4 v = reinterpret_cast<const float4*>(S.inv.sin_[sub][c])[y4];
                    float w0 = S.inv.sw[o0][c];
                    float w1 = S.inv.sw[o1][c];
                    acc0.x += w0*v.x; acc0.y += w0*v.y; acc0.z += w0*v.z; acc0.w += w0*v.w;
                    acc1.x += w1*v.x; acc1.y += w1*v.y; acc1.z += w1*v.z; acc1.w += w1*v.w;
                }
                float spec0[4], spec1[4];
                {
                    float g00 = S.inv.sG[sub][o0][0].x;
                    float g10 = S.inv.sG[sub][o1][0].x;
                    #pragma unroll
                    for (int j = 0; j < 4; j++){ spec0[j] = g00; spec1[j] = g10; }
                }
                // twiddles by double rotation: w(ky,j) = e^{i pi ky (4*y4+j)/32}
                float sy, cy; sincospif((float)y4/8.0f, &sy, &cy);
                float2 wy = make_float2(cy, sy);                  // e^{i pi y4/8}
                float su, cu; sincospif(1.0f/32.0f, &su, &cu);
                float2 runit = make_float2(cu, su);               // e^{i pi/32}
                float2 wstart = wy;
                float2 rky = runit;
                #pragma unroll
                for (int ky = 1; ky < 8; ky++){
                    float2 Gk0 = S.inv.sG[sub][o0][ky];
                    float2 Gk1 = S.inv.sG[sub][o1][ky];
                    float2 w = wstart;
                    #pragma unroll
                    for (int j = 0; j < 4; j++){
                        spec0[j] += 2.0f*(Gk0.x*w.x - Gk0.y*w.y);
                        spec1[j] += 2.0f*(Gk1.x*w.x - Gk1.y*w.y);
                        w = cmul(w, rky);
                    }
                    wstart = cmul(wstart, wy);
                    rky = cmul(rky, runit);
                }
                float bb0 = __ldg(wptb + l*32 + o0);
                float bb1 = __ldg(wptb + l*32 + o1);
                float4 r0, r1;
                r0.x = acc0.x + bb0 + spec0[0]*(1.0f/4096.0f);
                r0.y = acc0.y + bb0 + spec0[1]*(1.0f/4096.0f);
                r0.z = acc0.z + bb0 + spec0[2]*(1.0f/4096.0f);
                r0.w = acc0.w + bb0 + spec0[3]*(1.0f/4096.0f);
                r1.x = acc1.x + bb1 + spec1[0]*(1.0f/4096.0f);
                r1.y = acc1.y + bb1 + spec1[1]*(1.0f/4096.0f);
                r1.z = acc1.z + bb1 + spec1[2]*(1.0f/4096.0f);
                r1.w = acc1.w + bb1 + spec1[3]*(1.0f/4096.0f);
                if (dogelu){
                    r0.x = gelu(r0.x); r0.y = gelu(r0.y); r0.z = gelu(r0.z); r0.w = gelu(r0.w);
                    r1.x = gelu(r1.x); r1.y = gelu(r1.y); r1.z = gelu(r1.z); r1.w = gelu(r1.w);
                }
                reinterpret_cast<float4*>(outp + (size_t)o0*GP)[y4] = r0;
                reinterpret_cast<float4*>(outp + (size_t)o1*GP)[y4] = r1;
            }
        }
        gridbar();
        src ^= 1;
    }
    // src == 0: final h in g_h[0]

    // ================= NUFWD: block = (b,c), rotation twiddles ================
    {
        int bc = bk;
        const float4* hp = reinterpret_cast<const float4*>(g_h[src] + (size_t)bc*GP);
        float4* img4 = reinterpret_cast<float4*>(S.fwd.img);
        for (int i = tid; i < 1024; i += NT) img4[i] = hp[i];
        __syncthreads();
        for (int task = tid; task < 576; task += NT){
            int xx = task/9, bb2 = task - xx*9;
            int pb = bb2 + 57; if (pb >= 65) pb -= 65;
            const float4* row = reinterpret_cast<const float4*>(S.fwd.img + (xx << 6));
            float sr, cr; sincospif(-2.0f*(float)pb/65.0f, &sr, &cr);
            float2 r = make_float2(cr, sr);
            float2 w = make_float2(1.f, 0.f);
            float re = 0, im = 0;
            #pragma unroll
            for (int i = 0; i < 16; i++){
                float4 v = row[i];
                float2 w0 = w;
                float2 w1 = cmul(w0, r);
                float2 w2 = cmul(w1, r);
                float2 w3 = cmul(w2, r);
                w = cmul(w3, r);
                re += v.x*w0.x + v.y*w1.x + v.z*w2.x + v.w*w3.x;
                im += v.x*w0.y + v.y*w1.y + v.z*w2.y + v.w*w3.y;
            }
            S.fwd.t[xx][bb2] = make_float2(re, im);
        }
        __syncthreads();
        if (tid < 320){
            int task = tid >> 1, sub = tid & 1;
            int ai = task/9, bb2 = task - ai*9;
            int pa = ai + 57; if (pa >= 65) pa -= 65;
            float si, ci; sincospif(-2.0f*(float)(pa*sub)/65.0f, &si, &ci);
            float2 w = make_float2(ci, si);
            float ss, cs; sincospif(-4.0f*(float)pa/65.0f, &ss, &cs);
            float2 rs = make_float2(cs, ss);
            float re = 0, im = 0;
            #pragma unroll
            for (int i = 0; i < 32; i++){
                float2 tv = S.fwd.t[sub + (i << 1)][bb2 < 9 ? bb2 : 0];
                re += tv.x*w.x - tv.y*w.y;
                im += tv.x*w.y + tv.y*w.x;
                w = cmul(w, rs);
            }
            re += __shfl_down_sync(0xffffffffu, re, 1);
            im += __shfl_down_sync(0xffffffffu, im, 1);
            if (sub == 0 && task < 153)
                g_Fm[(size_t)bc*153 + task] = make_float2(re*(1.0f/65.0f), im*(1.0f/65.0f));
        }
    }
    gridbar();

    // ================= IMAGES+NUDFT (blocks 0..63) + FC12 (blocks 64..127, 2-thread split) ================
    if (bk < 64){
        int b = bk >> 4, s = bk & 15;
        const float2* Fb = g_Fm + (size_t)b*CN*153;
        if (tid < 145){
            if (tid < 136){
                int ai = tid >> 3, bi = tid & 7;
                const float2* w = reinterpret_cast<const float2*>(nw1 + (size_t)s*272 + ai*16 + bi*2);
                float re = 0, im = 0;
                #pragma unroll 8
                for (int c = 0; c < 32; c++){
                    float2 f = __ldg(Fb + c*153 + ai*9 + bi);
                    float2 wv = __ldg(w + (size_t)c*2176);
                    re += f.x*wv.x - f.y*wv.y;
                    im += f.x*wv.y + f.y*wv.x;
                }
                S.img.sim1[ai][bi] = make_float2(re, im);
            } else {
                int ai = tid - 136;
                const float2* w = reinterpret_cast<const float2*>(nw2 + (size_t)s*18 + ai*2);
                float re = 0, im = 0;
                #pragma unroll 8
                for (int c = 0; c < 32; c++){
                    float2 f = __ldg(Fb + c*153 + ai*9 + 8);
                    float2 wv = __ldg(w + (size_t)c*144);
                    re += f.x*wv.x - f.y*wv.y;
                    im += f.x*wv.y + f.y*wv.x;
                }
                S.img.sim2[ai] = make_float2(re, im);
            }
        }
        __syncthreads();
        if (tid < 289){
            int xx = tid/17, yy = tid%17;
            float2 v;
            if (yy < 8)       v = S.img.sim1[xx][yy];
            else if (yy > 8){ float2 u = S.img.sim1[16-xx][16-yy]; v = make_float2(u.x, -u.y); }
            else {
                if (xx < 8)        v = S.img.sim2[xx];
                else if (xx == 8)  v = make_float2(S.img.sim2[8].x, 0.0f);
                else             { float2 u = S.img.sim2[16-xx]; v = make_float2(u.x, -u.y); }
            }
            S.img.simg[tid] = v;
        }
        __syncthreads();
        int j0 = __ldg(sep + b*17 + s), j1 = __ldg(sep + b*17 + s + 1);
        float mn0 = g_mn[(b*SN+s)*2], mn1 = g_mn[(b*SN+s)*2+1];
        float mx0 = g_mx[(b*SN+s)*2], mx1 = g_mx[(b*SN+s)*2+1];
        float wS = __ldg(nw + s), bS = __ldg(nb + s);
        for (int j = j0 + tid; j < j1; j += NT){
            int p = __ldg(ind + (size_t)b*NYP + j);
            float l0 = __ldg(loc + ((size_t)b*NYP + p)*2);
            float l1 = __ldg(loc + ((size_t)b*NYP + p)*2 + 1);
            float om0 = (l0 - mn0)/(mx0 - mn0 + 1e-6f)*6.283185307179586f - 3.141592653589793f;
            float om1 = (l1 - mn1)/(mx1 - mn1 + 1e-6f)*6.283185307179586f - 3.141592653589793f;
            float sx, cx; sincosf(om0, &sx, &cx); float2 e0 = make_float2(cx, sx);
            float sy, cy; sincosf(om1, &sy, &cy); float2 e1 = make_float2(cy, sy);
            float2 ey[17];
            ey[8] = make_float2(1.f, 0.f);
            #pragma unroll
            for (int k = 9; k < 17; k++) ey[k] = cmul(ey[k-1], e1);
            #pragma unroll
            for (int k = 0; k < 8; k++) ey[k] = make_float2(ey[16-k].x, -ey[16-k].y);
            float2 e2v = cmul(e0, e0), e4v = cmul(e2v, e2v), e8v = cmul(e4v, e4v);
            float2 exc = make_float2(e8v.x, -e8v.y);
            float acc = 0;
            #pragma unroll
            for (int xx = 0; xx < 17; xx++){
                float rr = 0, ri = 0;
                #pragma unroll
                for (int yy = 0; yy < 17; yy++){
                    float2 a = S.img.simg[xx*17 + yy];
                    float2 e = ey[yy];
                    rr += a.x*e.x - a.y*e.y;
                    ri += a.x*e.y + a.y*e.x;
                }
                acc += rr*exc.x - ri*exc.y;
                exc = cmul(exc, e0);
            }
            g_nu[(size_t)b*NYP + p] = acc*(1.0f/17.0f)*wS + bS;
        }
    } else {
        // FC12 on 64 blocks, 2 threads per point (j-loop split 64/64, shfl combine)
        for (int i = tid; i < 4096; i += NT) S.fc12.sW1[i] = __ldg(Wfc1 + i);
        if (tid < 128){ S.fc12.sb1[tid] = __ldg(bfc1 + tid); S.fc12.sW2[tid] = __ldg(Wfc2 + tid); }
        __syncthreads();
        int pt = ((bk - 64)*NT + tid) >> 1;     // 0..16383
        int half = tid & 1;
        int b = pt >> 12, g = pt & (GP-1);
        float hv[32];
        #pragma unroll
        for (int c = 0; c < 32; c++) hv[c] = g_h[src][(size_t)(b*CN + c)*GP + g];
        float acc = 0;
        int jbase = half*64;
        #pragma unroll 4
        for (int jj = 0; jj < 64; jj++){
            int j = jbase + jj;
            float a = S.fc12.sb1[j];
            #pragma unroll
            for (int c = 0; c < 32; c++) a += S.fc12.sW1[j*32 + c]*hv[c];
            a = gelu(a);
            acc += a*S.fc12.sW2[j];
        }
        acc += __shfl_down_sync(0xffffffffu, acc, 1);
        if (half == 0) g_hl[pt] = acc + __ldg(bfc2);
    }
    gridbar();

    // ================= DE3: 4 rows per warp, interleaved ================
    {
        const float4* W0 = reinterpret_cast<const float4*>(Wde3 + (size_t)gwarp*GP);
        const float4* W1 = reinterpret_cast<const float4*>(Wde3 + (size_t)(gwarp+2048)*GP);
        const float4* W2 = reinterpret_cast<const float4*>(Wde3 + (size_t)(gwarp+4096)*GP);
        const float4* W3 = reinterpret_cast<const float4*>(Wde3 + (size_t)(gwarp+6144)*GP);
        float acc[4][4];
        #pragma unroll
        for (int r = 0; r < 4; r++)
            #pragma unroll
            for (int b = 0; b < 4; b++) acc[r][b] = 0.f;
        #pragma unroll 2
        for (int i = lane; i < GP/4; i += 32){
            float4 w0 = __ldg(W0 + i);
            float4 w1 = __ldg(W1 + i);
            float4 w2 = __ldg(W2 + i);
            float4 w3 = __ldg(W3 + i);
            #pragma unroll
            for (int b = 0; b < 4; b++){
                float4 h = *reinterpret_cast<const float4*>(g_hl + (size_t)b*GP + 4*i);
                acc[0][b] += w0.x*h.x + w0.y*h.y + w0.z*h.z + w0.w*h.w;
                acc[1][b] += w1.x*h.x + w1.y*h.y + w1.z*h.z + w1.w*h.w;
                acc[2][b] += w2.x*h.x + w2.y*h.y + w2.z*h.z + w2.w*h.w;
                acc[3][b] += w3.x*h.x + w3.y*h.y + w3.z*h.z + w3.w*h.w;
            }
        }
        #pragma unroll
        for (int r = 0; r < 4; r++){
            #pragma unroll
            for (int b = 0; b < 4; b++) acc[r][b] = wred(acc[r][b]);
        }
        if (lane == 0){
            #pragma unroll
            for (int r = 0; r < 4; r++){
                int row = gwarp + r*2048;
                float bv = __ldg(bde3 + row);
                #pragma unroll
                for (int b = 0; b < 4; b++)
                    out[(size_t)b*NYP + row] = acc[r][b] + bv + g_nu[(size_t)b*NYP + row];
            }
        }
    }
}

// ---------------- host launcher ----------------
extern "C" void kernel_launch(void* const* d_in, const int* in_sizes, int n_in,
                              void* d_out, int out_size){
    k_mega<<<NB, NT>>>(
        (const float*)d_in[0],  (const float*)d_in[1],
        (const int*)  d_in[2],  (const int*)  d_in[3],
        (const float*)d_in[4],  (const float*)d_in[5],
        (const float*)d_in[6],  (const float*)d_in[7],
        (const float*)d_in[8],  (const float*)d_in[9],
        (const float*)d_in[10], (const float*)d_in[11],
        (const float*)d_in[12], (const float*)d_in[13],
        (const float*)d_in[14], (const float*)d_in[15],
        (const float*)d_in[16], (const float*)d_in[17],
        (const float*)d_in[18], (const float*)d_in[19],
        (const float*)d_in[20], (const float*)d_in[21],
        (const float*)d_in[22], (const float*)d_in[23],
        (float*)d_out);
}